// round 14
// baseline (speedup 1.0000x reference)
#include <cuda_runtime.h>
#include <cuda_bf16.h>
#include <cstddef>
#include <cstdint>

// Problem constants (match reference)
#define BB  4
#define SS  1024
#define DD  1024
#define HH  16
#define DKV 64          // DK == DV == 64
#define NR  65          // 2*MAX_REL+1 relative buckets

// ---------------------------------------------------------------------------
// Scratch (static device globals; runtime allocation is forbidden)
// ---------------------------------------------------------------------------
__device__ float g_Q  [(size_t)BB * SS * DD];        // [B,S,H*DK]  projected q
__device__ float g_K  [(size_t)BB * SS * DD];        // [B,S,H*DK]  projected k
__device__ float g_V  [(size_t)BB * SS * DD];        // [B,S,H*DV]  projected v
__device__ float g_CTX[(size_t)BB * SS * DD];        // [B,S,H*DV]  context
__device__ float g_QE [(size_t)BB * HH * SS * NR];   // [BH,S,65]   0.125 * q.emb_k[r]
__device__ float g_AW [(size_t)BB * HH * SS * NR];   // [BH,S,65]   bucket-summed attn

// split-bf16 staging (reused across the 4 tensor GEMMs; stream-serialized)
__device__ __nv_bfloat16 g_Ah[(size_t)BB * SS * DD];   // A hi  [4096,1024]
__device__ __nv_bfloat16 g_Al[(size_t)BB * SS * DD];   // A lo
__device__ __nv_bfloat16 g_Bh[(size_t)DD * DD];        // W^T hi [N=1024,K=1024]
__device__ __nv_bfloat16 g_Bl[(size_t)DD * DD];        // W^T lo

// ===========================================================================
// PTX helpers — baseline (non-'a') ISA only: ldmatrix / mma.sync / cp.async
// ===========================================================================
__device__ __forceinline__ uint32_t smem_u32(const void* p) {
    uint32_t a;
    asm("{ .reg .u64 t; cvta.to.shared.u64 t, %1; cvt.u32.u64 %0, t; }"
        : "=r"(a) : "l"(p));
    return a;
}

#define CP_ASYNC16(dst, src) \
    asm volatile("cp.async.cg.shared.global [%0], [%1], 16;" \
                 :: "r"(dst), "l"(src))
#define CP_COMMIT()  asm volatile("cp.async.commit_group;" ::: "memory")
#define CP_WAIT0()   asm volatile("cp.async.wait_group 0;"  ::: "memory")

#define LDSM_X4(r0, r1, r2, r3, addr) \
    asm volatile("ldmatrix.sync.aligned.m8n8.x4.shared.b16 {%0,%1,%2,%3}, [%4];" \
                 : "=r"(r0), "=r"(r1), "=r"(r2), "=r"(r3) : "r"(addr))

// D(f32) += A(bf16,row) @ B(bf16,col);  c[4] in-place accumulate
#define MMA16816(c, a, b) \
    asm volatile("mma.sync.aligned.m16n8k16.row.col.f32.bf16.bf16.f32 " \
                 "{%0,%1,%2,%3}, {%4,%5,%6,%7}, {%8,%9}, {%0,%1,%2,%3};" \
                 : "+f"((c)[0]), "+f"((c)[1]), "+f"((c)[2]), "+f"((c)[3]) \
                 : "r"((a)[0]), "r"((a)[1]), "r"((a)[2]), "r"((a)[3]), \
                   "r"((b)[0]), "r"((b)[1]))

// split one fp32 into hi/lo bf16
__device__ __forceinline__ void split1(float v, __nv_bfloat16& h, __nv_bfloat16& l) {
    h = __float2bfloat16(v);
    l = __float2bfloat16(v - __bfloat162float(h));
}
// split float4 into two packed uint2 (4 bf16 each)
__device__ __forceinline__ void split4(float4 x, uint2& H, uint2& L) {
    __nv_bfloat16 h0, h1, h2, h3, l0, l1, l2, l3;
    split1(x.x, h0, l0); split1(x.y, h1, l1);
    split1(x.z, h2, l2); split1(x.w, h3, l3);
    __nv_bfloat162 ha = __halves2bfloat162(h0, h1), hb = __halves2bfloat162(h2, h3);
    __nv_bfloat162 la = __halves2bfloat162(l0, l1), lb = __halves2bfloat162(l2, l3);
    H.x = *reinterpret_cast<uint32_t*>(&ha); H.y = *reinterpret_cast<uint32_t*>(&hb);
    L.x = *reinterpret_cast<uint32_t*>(&la); L.y = *reinterpret_cast<uint32_t*>(&lb);
}

// ===========================================================================
// Split kernels: fp32 -> (hi, lo) bf16
// ===========================================================================
__global__ __launch_bounds__(256) void split_kernel(
    const float4* __restrict__ X, uint2* __restrict__ hi, uint2* __restrict__ lo)
{
    int i = blockIdx.x * 256 + threadIdx.x;
    uint2 H, L;
    split4(X[i], H, L);
    hi[i] = H; lo[i] = L;
}

// W[K,N] fp32 -> Wt_hi/Wt_lo [N,K] bf16 (transpose + split)
__global__ __launch_bounds__(256) void transpose_split_kernel(
    const float* __restrict__ W,
    __nv_bfloat16* __restrict__ th, __nv_bfloat16* __restrict__ tl)
{
    __shared__ float t[32][33];
    const int n0 = blockIdx.x * 32, k0 = blockIdx.y * 32;
    const int tx = threadIdx.x, ty = threadIdx.y;
#pragma unroll
    for (int i = 0; i < 32; i += 8)
        t[ty + i][tx] = W[(size_t)(k0 + ty + i) * DD + n0 + tx];
    __syncthreads();
#pragma unroll
    for (int i = 0; i < 32; i += 8) {
        float v = t[tx][ty + i];
        __nv_bfloat16 h, l; split1(v, h, l);
        th[(size_t)(n0 + ty + i) * DD + k0 + tx] = h;
        tl[(size_t)(n0 + ty + i) * DD + k0 + tx] = l;
    }
}

// ===========================================================================
// mma.sync split-bf16 GEMM: C[4096,1024] = A @ W + bias  (unchanged from R12)
// ===========================================================================
#define MG_BK      32
#define MG_NCHUNK  (DD / MG_BK)
#define MG_ROW_B   80
#define MG_TILE_B  (128 * MG_ROW_B)
#define MG_STAGE_B (4 * MG_TILE_B)
#define MG_SMEM    (2 * MG_STAGE_B)

__global__ __launch_bounds__(256, 1) void mgemm_kernel(
    const __nv_bfloat16* __restrict__ Ah, const __nv_bfloat16* __restrict__ Al,
    const __nv_bfloat16* __restrict__ Bh, const __nv_bfloat16* __restrict__ Bl,
    const float* __restrict__ bias, float* __restrict__ C)
{
    extern __shared__ char smem[];
    const uint32_t sbase = smem_u32(smem);
    const int tid  = threadIdx.x;
    const int lane = tid & 31, wid = tid >> 5;
    const int wm   = wid >> 2, wn = wid & 3;
    const int m0   = blockIdx.y * 128;
    const int n0   = blockIdx.x * 128;

    const __nv_bfloat16* gsrc[4] = {Ah, Al, Bh, Bl};
    const int grow[4] = {m0, m0, n0, n0};

    auto load_chunk = [&](int i, int st) {
        const int k0 = i * MG_BK;
#pragma unroll
        for (int t = 0; t < 4; t++) {
            const uint32_t tb = sbase + st * MG_STAGE_B + t * MG_TILE_B;
            const __nv_bfloat16* G = gsrc[t];
            const int gr = grow[t];
#pragma unroll
            for (int p = 0; p < 2; p++) {
                int idx = tid + p * 256;
                int r = idx >> 2, c = idx & 3;
                uint32_t dst = tb + r * MG_ROW_B + c * 16;
                const void* src = G + (size_t)(gr + r) * DD + k0 + c * 8;
                CP_ASYNC16(dst, src);
            }
        }
    };

    float acc[4][4][4] = {};
    load_chunk(0, 0);
    CP_COMMIT();

    const int lr = lane & 15, lh = lane >> 4;

    for (int i = 0; i < MG_NCHUNK; i++) {
        const int st = i & 1;
        CP_WAIT0();
        __syncthreads();
        if (i + 1 < MG_NCHUNK) { load_chunk(i + 1, st ^ 1); CP_COMMIT(); }

        const uint32_t stb = sbase + st * MG_STAGE_B;
#pragma unroll
        for (int ks = 0; ks < 2; ks++) {
            uint32_t ah[4][4], al[4][4], bh[4][2], bl[4][2];
            const uint32_t kb = ks * 32 + lh * 16;
#pragma unroll
            for (int f = 0; f < 4; f++) {
                uint32_t rowb = (wm * 64 + f * 16 + lr) * MG_ROW_B + kb;
                LDSM_X4(ah[f][0], ah[f][1], ah[f][2], ah[f][3],
                        stb + 0 * MG_TILE_B + rowb);
                LDSM_X4(al[f][0], al[f][1], al[f][2], al[f][3],
                        stb + 1 * MG_TILE_B + rowb);
            }
#pragma unroll
            for (int h = 0; h < 2; h++) {
                uint32_t rowb = (wn * 32 + h * 16 + lr) * MG_ROW_B + kb;
                uint32_t r0, r1, r2, r3;
                LDSM_X4(r0, r1, r2, r3, stb + 2 * MG_TILE_B + rowb);
                bh[h * 2][0] = r0; bh[h * 2 + 1][0] = r1;
                bh[h * 2][1] = r2; bh[h * 2 + 1][1] = r3;
                LDSM_X4(r0, r1, r2, r3, stb + 3 * MG_TILE_B + rowb);
                bl[h * 2][0] = r0; bl[h * 2 + 1][0] = r1;
                bl[h * 2][1] = r2; bl[h * 2 + 1][1] = r3;
            }
#pragma unroll
            for (int mf = 0; mf < 4; mf++)
#pragma unroll
                for (int nf = 0; nf < 4; nf++)
                    MMA16816(acc[mf][nf], ah[mf], bh[nf]);
#pragma unroll
            for (int mf = 0; mf < 4; mf++)
#pragma unroll
                for (int nf = 0; nf < 4; nf++)
                    MMA16816(acc[mf][nf], ah[mf], bl[nf]);
#pragma unroll
            for (int mf = 0; mf < 4; mf++)
#pragma unroll
                for (int nf = 0; nf < 4; nf++)
                    MMA16816(acc[mf][nf], al[mf], bh[nf]);
        }
        __syncthreads();
    }

    const int g = lane >> 2, tq = lane & 3;
#pragma unroll
    for (int mf = 0; mf < 4; mf++) {
        const int row = m0 + wm * 64 + mf * 16 + g;
#pragma unroll
        for (int nf = 0; nf < 4; nf++) {
            const int col = n0 + wn * 32 + nf * 8 + tq * 2;
            const float2 bv = *reinterpret_cast<const float2*>(bias + col);
            float2 o0, o1;
            o0.x = acc[mf][nf][0] + bv.x; o0.y = acc[mf][nf][1] + bv.y;
            o1.x = acc[mf][nf][2] + bv.x; o1.y = acc[mf][nf][3] + bv.y;
            *reinterpret_cast<float2*>(C + (size_t)row * DD + col)       = o0;
            *reinterpret_cast<float2*>(C + (size_t)(row + 8) * DD + col) = o1;
        }
    }
}

// ---------------------------------------------------------------------------
// qe[bh,q,r] = 0.125 * sum_d Q[b,q,h*64+d] * emb_k[r,d]
// Register-blocked 4x4: block = 64 rows, 256 threads (ty: 16 x 4 rows,
// tx: 16 x {tx, tx+16, tx+32, tx+48} buckets; tx==0 also handles r=64).
// ---------------------------------------------------------------------------
__global__ __launch_bounds__(256) void qe_kernel(const float* __restrict__ emb_k)
{
    __shared__ float Qs[64][65];
    __shared__ float E [NR][66];
    const int tid = threadIdx.x;
    const int g0  = blockIdx.x * 64;
    const int bh  = g0 / SS;
    const int qb  = g0 % SS;
    const int b   = bh / HH, h = bh % HH;

    for (int idx = tid; idx < NR * 64; idx += 256) {
        int r = idx >> 6, d = idx & 63;
        E[r][d] = emb_k[idx];
    }
    for (int idx = tid; idx < 64 * 64; idx += 256) {
        int r = idx >> 6, d = idx & 63;
        Qs[r][d] = g_Q[(size_t)(b * SS + qb + r) * DD + h * DKV + d];
    }
    __syncthreads();

    const int ty = tid >> 4, tx = tid & 15;
    float acc[4][4] = {};
    float acc4[4]   = {};
#pragma unroll 8
    for (int d = 0; d < 64; d++) {
        float qv[4];
#pragma unroll
        for (int i = 0; i < 4; i++) qv[i] = Qs[4 * ty + i][d];
#pragma unroll
        for (int j = 0; j < 4; j++) {
            float ev = E[tx + 16 * j][d];
#pragma unroll
            for (int i = 0; i < 4; i++) acc[i][j] = fmaf(qv[i], ev, acc[i][j]);
        }
        if (tx == 0) {
            float e4 = E[64][d];
#pragma unroll
            for (int i = 0; i < 4; i++) acc4[i] = fmaf(qv[i], e4, acc4[i]);
        }
    }
#pragma unroll
    for (int i = 0; i < 4; i++) {
        size_t rowo = (size_t)(g0 + 4 * ty + i) * NR;
#pragma unroll
        for (int j = 0; j < 4; j++)
            g_QE[rowo + tx + 16 * j] = 0.125f * acc[i][j];
        if (tx == 0) g_QE[rowo + 64] = 0.125f * acc4[i];
    }
}

// ===========================================================================
// scores (tensor): attn_raw[bh,q,k] = (Q/8).K + qe_scaled[q, clip(k-q)+32]
// CTA tile 128q x 128k, K=64 resident. Q,K converted fp32->split-bf16 at
// smem store (Q pre-scaled by 1/8). qe staged in smem for the epilogue gather.
// Warp grid 2x4 (64x32 per warp), 3 split passes.
// ===========================================================================
#define SC_PITCH  144
#define SC_TILE_B (128 * SC_PITCH)        // 18432
#define SC_QE_OFF (4 * SC_TILE_B)         // 73728
#define SC_SMEM   (SC_QE_OFF + 128 * 66 * 4)   // 107520

__global__ __launch_bounds__(256, 1) void scores_mma_kernel(float* __restrict__ attn)
{
    extern __shared__ char smem[];
    const uint32_t sbase = smem_u32(smem);
    float* qe_s = reinterpret_cast<float*>(smem + SC_QE_OFF);
    const int tid  = threadIdx.x;
    const int lane = tid & 31, wid = tid >> 5;
    const int wm   = wid >> 2, wn = wid & 3;
    const int bh = blockIdx.z;
    const int b  = bh / HH, h = bh % HH;
    const int q0 = blockIdx.y * 128;
    const int k0 = blockIdx.x * 128;

    // --- load + convert Q (x0.125), K into split-bf16 smem tiles ---
#pragma unroll
    for (int p = 0; p < 8; p++) {
        int idx = tid + p * 256;            // 2048 float4
        int r = idx >> 4, c = idx & 15;
        float4 q4 = *reinterpret_cast<const float4*>(
            &g_Q[(size_t)(b * SS + q0 + r) * DD + h * DKV + c * 4]);
        q4.x *= 0.125f; q4.y *= 0.125f; q4.z *= 0.125f; q4.w *= 0.125f;
        uint2 H, L; split4(q4, H, L);
        *reinterpret_cast<uint2*>(smem + 0 * SC_TILE_B + r * SC_PITCH + c * 8) = H;
        *reinterpret_cast<uint2*>(smem + 1 * SC_TILE_B + r * SC_PITCH + c * 8) = L;
        float4 k4 = *reinterpret_cast<const float4*>(
            &g_K[(size_t)(b * SS + k0 + r) * DD + h * DKV + c * 4]);
        split4(k4, H, L);
        *reinterpret_cast<uint2*>(smem + 2 * SC_TILE_B + r * SC_PITCH + c * 8) = H;
        *reinterpret_cast<uint2*>(smem + 3 * SC_TILE_B + r * SC_PITCH + c * 8) = L;
    }
    // --- stage qe rows for this q-tile ---
#pragma unroll
    for (int p = 0; p < 33; p++) {
        int idx = tid + p * 256;            // 8320 floats
        if (idx < 128 * NR) {
            int r = idx / NR, rr = idx - r * NR;
            qe_s[r * 66 + rr] = g_QE[((size_t)bh * SS + q0 + r) * NR + rr];
        }
    }
    __syncthreads();

    float acc[4][4][4] = {};
    const int lr = lane & 15, lh = lane >> 4;
#pragma unroll
    for (int ks = 0; ks < 4; ks++) {
        uint32_t ah[4][4], al[4][4], bhf[4][2], blf[4][2];
        const uint32_t kb = ks * 32 + lh * 16;
#pragma unroll
        for (int f = 0; f < 4; f++) {
            uint32_t rowb = (wm * 64 + f * 16 + lr) * SC_PITCH + kb;
            LDSM_X4(ah[f][0], ah[f][1], ah[f][2], ah[f][3], sbase + 0 * SC_TILE_B + rowb);
            LDSM_X4(al[f][0], al[f][1], al[f][2], al[f][3], sbase + 1 * SC_TILE_B + rowb);
        }
#pragma unroll
        for (int hh = 0; hh < 2; hh++) {
            uint32_t rowb = (wn * 32 + hh * 16 + lr) * SC_PITCH + kb;
            uint32_t r0, r1, r2, r3;
            LDSM_X4(r0, r1, r2, r3, sbase + 2 * SC_TILE_B + rowb);
            bhf[hh * 2][0] = r0; bhf[hh * 2 + 1][0] = r1;
            bhf[hh * 2][1] = r2; bhf[hh * 2 + 1][1] = r3;
            LDSM_X4(r0, r1, r2, r3, sbase + 3 * SC_TILE_B + rowb);
            blf[hh * 2][0] = r0; blf[hh * 2 + 1][0] = r1;
            blf[hh * 2][1] = r2; blf[hh * 2 + 1][1] = r3;
        }
#pragma unroll
        for (int mf = 0; mf < 4; mf++)
#pragma unroll
            for (int nf = 0; nf < 4; nf++)
                MMA16816(acc[mf][nf], ah[mf], bhf[nf]);
#pragma unroll
        for (int mf = 0; mf < 4; mf++)
#pragma unroll
            for (int nf = 0; nf < 4; nf++)
                MMA16816(acc[mf][nf], ah[mf], blf[nf]);
#pragma unroll
        for (int mf = 0; mf < 4; mf++)
#pragma unroll
            for (int nf = 0; nf < 4; nf++)
                MMA16816(acc[mf][nf], al[mf], bhf[nf]);
    }

    // --- epilogue: add relative-key term (already scaled), store fp32 ---
    const int g = lane >> 2, tq = lane & 3;
    const int brel = k0 - q0;
#pragma unroll
    for (int mf = 0; mf < 4; mf++) {
        const int row  = wm * 64 + mf * 16 + g;      // local q (this and +8)
#pragma unroll
        for (int nf = 0; nf < 4; nf++) {
            const int col = wn * 32 + nf * 8 + tq * 2;
            int r0 = brel + col - row;
            int i00 = min(max(r0,     -32), 32) + 32;
            int i01 = min(max(r0 + 1, -32), 32) + 32;
            int i10 = min(max(r0 - 8, -32), 32) + 32;
            int i11 = min(max(r0 - 7, -32), 32) + 32;
            float2 o0, o1;
            o0.x = acc[mf][nf][0] + qe_s[row * 66 + i00];
            o0.y = acc[mf][nf][1] + qe_s[row * 66 + i01];
            o1.x = acc[mf][nf][2] + qe_s[(row + 8) * 66 + i10];
            o1.y = acc[mf][nf][3] + qe_s[(row + 8) * 66 + i11];
            *reinterpret_cast<float2*>(
                &attn[((size_t)bh * SS + q0 + row) * SS + k0 + col]) = o0;
            *reinterpret_cast<float2*>(
                &attn[((size_t)bh * SS + q0 + row + 8) * SS + k0 + col]) = o1;
        }
    }
}

// ---------------------------------------------------------------------------
// FMA-pipe exp (degree-7, rel err ~1.3e-6). Valid for x <= 0.
// ---------------------------------------------------------------------------
__device__ __forceinline__ float fast_exp_neg(float x)
{
    x = fmaxf(x, -87.0f);
    float y = x * 1.4426950408889634f;
    float n = floorf(y);
    float f = y - n;
    float p = 1.5252734e-5f;
    p = fmaf(p, f, 1.5403530e-4f);
    p = fmaf(p, f, 1.3333558e-3f);
    p = fmaf(p, f, 9.6181291e-3f);
    p = fmaf(p, f, 5.5504109e-2f);
    p = fmaf(p, f, 2.4022651e-1f);
    p = fmaf(p, f, 6.9314718e-1f);
    p = fmaf(p, f, 1.0f);
    int e = (int)n;
    float sc = __int_as_float((e + 127) << 23);
    return p * sc;
}

// ---------------------------------------------------------------------------
// Row softmax in-place + relative-bucket accumulation.
// ---------------------------------------------------------------------------
__global__ __launch_bounds__(256) void softmax_aw_kernel(float* __restrict__ attn)
{
    const size_t g = blockIdx.x;
    const int q   = (int)(g & (SS - 1));
    const int tid = threadIdx.x;
    float* row = attn + g * SS;

    __shared__ float red[256];
    __shared__ float aw_s[NR];

    float v[4];
    float m = -1e30f;
#pragma unroll
    for (int i = 0; i < 4; i++) {
        v[i] = row[tid + i * 256];
        m = fmaxf(m, v[i]);
    }
    red[tid] = m; __syncthreads();
    for (int s = 128; s > 0; s >>= 1) {
        if (tid < s) red[tid] = fmaxf(red[tid], red[tid + s]);
        __syncthreads();
    }
    m = red[0]; __syncthreads();

    float sum = 0.f;
#pragma unroll
    for (int i = 0; i < 4; i++) {
        v[i] = fast_exp_neg(v[i] - m);
        sum += v[i];
    }
    red[tid] = sum; __syncthreads();
    for (int s = 128; s > 0; s >>= 1) {
        if (tid < s) red[tid] += red[tid + s];
        __syncthreads();
    }
    const float inv = 1.0f / red[0];
    __syncthreads();

    if (tid < NR) aw_s[tid] = 0.f;
    __syncthreads();

    float l0 = 0.f, l64 = 0.f;
#pragma unroll
    for (int i = 0; i < 4; i++) {
        int k = tid + i * 256;
        float p = v[i] * inv;
        row[k] = p;
        int dlt = k - q;
        if (dlt <= -32)      l0  += p;
        else if (dlt >= 32)  l64 += p;
        else                 aw_s[dlt + 32] = p;
    }

    red[tid] = l0; __syncthreads();
    for (int s = 128; s > 0; s >>= 1) {
        if (tid < s) red[tid] += red[tid + s];
        __syncthreads();
    }
    float t0 = red[0]; __syncthreads();

    red[tid] = l64; __syncthreads();
    for (int s = 128; s > 0; s >>= 1) {
        if (tid < s) red[tid] += red[tid + s];
        __syncthreads();
    }
    float t64 = red[0]; __syncthreads();

    if (tid == 0) { aw_s[0] += t0; aw_s[NR - 1] += t64; }
    __syncthreads();

    if (tid < NR) g_AW[g * NR + tid] = aw_s[tid];
}

// ===========================================================================
// ctx (tensor): ctx = attn @ V + aw @ emb_v, fused as one GEMM with the
// K-dimension extended 1024 -> 1024+96 (chunks 32..34 carry aw / emb_v,
// zero-padded past bucket 64). attn/V/aw/emb_v are converted fp32->split-bf16
// at smem-store time; V and emb_v stored transposed ([d][k]).
// CTA tile 128q x 64d, BK=32, double-buffered. Warp grid 4x2 (32x32 each).
// ===========================================================================
#define CT_PITCH   80
#define CT_AT_B    (128 * CT_PITCH)                  // 10240
#define CT_VT_B    (64 * CT_PITCH)                   // 5120
#define CT_STAGE_B (2 * CT_AT_B + 2 * CT_VT_B)       // 30720
#define CT_SMEM    (2 * CT_STAGE_B)                  // 61440
#define CT_NCHUNK  35                                // 32 main + 3 tail (96 ext-k)

__global__ __launch_bounds__(256, 1) void ctx_mma_kernel(
    const float* __restrict__ attn, const float* __restrict__ emb_v)
{
    extern __shared__ char smem[];
    const uint32_t sbase = smem_u32(smem);
    const int tid  = threadIdx.x;
    const int lane = tid & 31, wid = tid >> 5;
    const int wm   = wid & 3, wn = wid >> 2;        // 4 x 2 warp grid
    const int bh = blockIdx.y;
    const int b  = bh / HH, h = bh % HH;
    const int q0 = blockIdx.x * 128;

    float rA[16], rV[8];

    auto ld = [&](int i) {
        if (i < 32) {
#pragma unroll
            for (int p = 0; p < 4; p++) {
                int idx = tid + p * 256;             // 1024 float4 (attn 128x32)
                int r = idx >> 3, c = idx & 7;
                float4 v = *reinterpret_cast<const float4*>(
                    &attn[((size_t)bh * SS + q0 + r) * SS + i * 32 + c * 4]);
                rA[p * 4] = v.x; rA[p * 4 + 1] = v.y;
                rA[p * 4 + 2] = v.z; rA[p * 4 + 3] = v.w;
            }
#pragma unroll
            for (int p = 0; p < 2; p++) {
                int idx = tid + p * 256;             // 512 float4 (V 32x64)
                int k = idx >> 4, c = idx & 15;
                float4 v = *reinterpret_cast<const float4*>(
                    &g_V[(size_t)(b * SS + i * 32 + k) * DD + h * DKV + c * 4]);
                rV[p * 4] = v.x; rV[p * 4 + 1] = v.y;
                rV[p * 4 + 2] = v.z; rV[p * 4 + 3] = v.w;
            }
        } else {
            const int kb = (i - 32) * 32;
#pragma unroll
            for (int p = 0; p < 16; p++) {
                int idx = tid + p * 256;             // 4096 scalars (aw 128x32)
                int r = idx >> 5, c = idx & 31;
                int kl = kb + c;
                rA[p] = (kl < NR)
                    ? g_AW[((size_t)bh * SS + q0 + r) * NR + kl] : 0.f;
            }
#pragma unroll
            for (int p = 0; p < 8; p++) {
                int idx = tid + p * 256;             // 2048 scalars (emb_v 32x64)
                int k = idx >> 6, d = idx & 63;
                int kl = kb + k;
                rV[p] = (kl < NR) ? emb_v[kl * DKV + d] : 0.f;
            }
        }
    };

    auto st = [&](int i, int s) {
        char* sb = smem + s * CT_STAGE_B;
        if (i < 32) {
#pragma unroll
            for (int p = 0; p < 4; p++) {
                int idx = tid + p * 256;
                int r = idx >> 3, c = idx & 7;
                float4 v = make_float4(rA[p * 4], rA[p * 4 + 1],
                                       rA[p * 4 + 2], rA[p * 4 + 3]);
                uint2 H, L; split4(v, H, L);
                *reinterpret_cast<uint2*>(sb + r * CT_PITCH + c * 8) = H;
                *reinterpret_cast<uint2*>(sb + CT_AT_B + r * CT_PITCH + c * 8) = L;
            }
#pragma unroll
            for (int p = 0; p < 2; p++) {
                int idx = tid + p * 256;
                int k = idx >> 4, c = idx & 15;
#pragma unroll
                for (int j = 0; j < 4; j++) {
                    __nv_bfloat16 hh, ll; split1(rV[p * 4 + j], hh, ll);
                    int d = c * 4 + j;
                    *reinterpret_cast<__nv_bfloat16*>(
                        sb + 2 * CT_AT_B + d * CT_PITCH + k * 2) = hh;
                    *reinterpret_cast<__nv_bfloat16*>(
                        sb + 2 * CT_AT_B + CT_VT_B + d * CT_PITCH + k * 2) = ll;
                }
            }
        } else {
#pragma unroll
            for (int p = 0; p < 16; p++) {
                int idx = tid + p * 256;
                int r = idx >> 5, c = idx & 31;
                __nv_bfloat16 hh, ll; split1(rA[p], hh, ll);
                *reinterpret_cast<__nv_bfloat16*>(sb + r * CT_PITCH + c * 2) = hh;
                *reinterpret_cast<__nv_bfloat16*>(
                    sb + CT_AT_B + r * CT_PITCH + c * 2) = ll;
            }
#pragma unroll
            for (int p = 0; p < 8; p++) {
                int idx = tid + p * 256;
                int k = idx >> 6, d = idx & 63;
                __nv_bfloat16 hh, ll; split1(rV[p], hh, ll);
                *reinterpret_cast<__nv_bfloat16*>(
                    sb + 2 * CT_AT_B + d * CT_PITCH + k * 2) = hh;
                *reinterpret_cast<__nv_bfloat16*>(
                    sb + 2 * CT_AT_B + CT_VT_B + d * CT_PITCH + k * 2) = ll;
            }
        }
    };

    ld(0); st(0, 0);
    __syncthreads();

    float acc[2][4][4] = {};
    const int lr = lane & 15, lh = lane >> 4;

    for (int i = 0; i < CT_NCHUNK; i++) {
        const int s = i & 1;
        if (i + 1 < CT_NCHUNK) ld(i + 1);          // LDG overlaps MMA

        const uint32_t stb = sbase + s * CT_STAGE_B;
#pragma unroll
        for (int ks = 0; ks < 2; ks++) {
            uint32_t ah[2][4], al[2][4], bhf[4][2], blf[4][2];
            const uint32_t kb = ks * 32 + lh * 16;
#pragma unroll
            for (int f = 0; f < 2; f++) {
                uint32_t rowb = (wm * 32 + f * 16 + lr) * CT_PITCH + kb;
                LDSM_X4(ah[f][0], ah[f][1], ah[f][2], ah[f][3], stb + rowb);
                LDSM_X4(al[f][0], al[f][1], al[f][2], al[f][3],
                        stb + CT_AT_B + rowb);
            }
#pragma unroll
            for (int hh = 0; hh < 2; hh++) {
                uint32_t rowb = (wn * 32 + hh * 16 + lr) * CT_PITCH + kb;
                uint32_t r0, r1, r2, r3;
                LDSM_X4(r0, r1, r2, r3, stb + 2 * CT_AT_B + rowb);
                bhf[hh * 2][0] = r0; bhf[hh * 2 + 1][0] = r1;
                bhf[hh * 2][1] = r2; bhf[hh * 2 + 1][1] = r3;
                LDSM_X4(r0, r1, r2, r3, stb + 2 * CT_AT_B + CT_VT_B + rowb);
                blf[hh * 2][0] = r0; blf[hh * 2 + 1][0] = r1;
                blf[hh * 2][1] = r2; blf[hh * 2 + 1][1] = r3;
            }
#pragma unroll
            for (int mf = 0; mf < 2; mf++)
#pragma unroll
                for (int nf = 0; nf < 4; nf++)
                    MMA16816(acc[mf][nf], ah[mf], bhf[nf]);
#pragma unroll
            for (int mf = 0; mf < 2; mf++)
#pragma unroll
                for (int nf = 0; nf < 4; nf++)
                    MMA16816(acc[mf][nf], ah[mf], blf[nf]);
#pragma unroll
            for (int mf = 0; mf < 2; mf++)
#pragma unroll
                for (int nf = 0; nf < 4; nf++)
                    MMA16816(acc[mf][nf], al[mf], bhf[nf]);
        }
        if (i + 1 < CT_NCHUNK) st(i + 1, s ^ 1);
        __syncthreads();
    }

    // epilogue -> g_CTX
    const int g = lane >> 2, tq = lane & 3;
#pragma unroll
    for (int mf = 0; mf < 2; mf++) {
        const int row = q0 + wm * 32 + mf * 16 + g;
#pragma unroll
        for (int nf = 0; nf < 4; nf++) {
            const int col = wn * 32 + nf * 8 + tq * 2;
            float2 o0 = make_float2(acc[mf][nf][0], acc[mf][nf][1]);
            float2 o1 = make_float2(acc[mf][nf][2], acc[mf][nf][3]);
            *reinterpret_cast<float2*>(
                &g_CTX[(size_t)(b * SS + row) * DD + h * DKV + col]) = o0;
            *reinterpret_cast<float2*>(
                &g_CTX[(size_t)(b * SS + row + 8) * DD + h * DKV + col]) = o1;
        }
    }
}

// ---------------------------------------------------------------------------
// kernel_launch
// Inputs: key, value, query, Wk, bk, Wq, bq, Wv, bv, Wo, bo, emb_k, emb_v
// Output: concat(final_output [B*S*D], attn [B*H*S*S]) float32
// ---------------------------------------------------------------------------
extern "C" void kernel_launch(void* const* d_in, const int* in_sizes, int n_in,
                              void* d_out, int out_size)
{
    (void)in_sizes; (void)n_in; (void)out_size;
    const float* key   = (const float*)d_in[0];
    const float* value = (const float*)d_in[1];
    const float* query = (const float*)d_in[2];
    const float* Wk    = (const float*)d_in[3];
    const float* bk    = (const float*)d_in[4];
    const float* Wq    = (const float*)d_in[5];
    const float* bq    = (const float*)d_in[6];
    const float* Wv    = (const float*)d_in[7];
    const float* bv    = (const float*)d_in[8];
    const float* Wo    = (const float*)d_in[9];
    const float* bo    = (const float*)d_in[10];
    const float* emb_k = (const float*)d_in[11];
    const float* emb_v = (const float*)d_in[12];

    float* out  = (float*)d_out;
    float* attn = out + (size_t)BB * SS * DD;

    float *pQ, *pK, *pV, *pCTX;
    cudaGetSymbolAddress((void**)&pQ,   g_Q);
    cudaGetSymbolAddress((void**)&pK,   g_K);
    cudaGetSymbolAddress((void**)&pV,   g_V);
    cudaGetSymbolAddress((void**)&pCTX, g_CTX);
    __nv_bfloat16 *pAh, *pAl, *pBh, *pBl;
    cudaGetSymbolAddress((void**)&pAh, g_Ah);
    cudaGetSymbolAddress((void**)&pAl, g_Al);
    cudaGetSymbolAddress((void**)&pBh, g_Bh);
    cudaGetSymbolAddress((void**)&pBl, g_Bl);

    cudaFuncSetAttribute(mgemm_kernel,
                         cudaFuncAttributeMaxDynamicSharedMemorySize, MG_SMEM);
    cudaFuncSetAttribute(scores_mma_kernel,
                         cudaFuncAttributeMaxDynamicSharedMemorySize, SC_SMEM);
    cudaFuncSetAttribute(ctx_mma_kernel,
                         cudaFuncAttributeMaxDynamicSharedMemorySize, CT_SMEM);

    const int M = BB * SS;                       // 4096
    dim3 thr(256);
    dim3 gMG(DD / 128, M / 128);                 // (8, 32)
    dim3 gTS(DD / 32, DD / 32);                  // (32, 32)
    dim3 bTS(32, 8);
    const int nA4 = (M * DD) / 4;

    // ---- projections (mma.sync split-bf16) ----
    split_kernel<<<nA4 / 256, thr>>>((const float4*)query, (uint2*)pAh, (uint2*)pAl);
    transpose_split_kernel<<<gTS, bTS>>>(Wq, pBh, pBl);
    mgemm_kernel<<<gMG, thr, MG_SMEM>>>(pAh, pAl, pBh, pBl, bq, pQ);

    split_kernel<<<nA4 / 256, thr>>>((const float4*)key, (uint2*)pAh, (uint2*)pAl);
    transpose_split_kernel<<<gTS, bTS>>>(Wk, pBh, pBl);
    mgemm_kernel<<<gMG, thr, MG_SMEM>>>(pAh, pAl, pBh, pBl, bk, pK);

    split_kernel<<<nA4 / 256, thr>>>((const float4*)value, (uint2*)pAh, (uint2*)pAl);
    transpose_split_kernel<<<gTS, bTS>>>(Wv, pBh, pBl);
    mgemm_kernel<<<gMG, thr, MG_SMEM>>>(pAh, pAl, pBh, pBl, bv, pV);

    // ---- relative-key projections qe (pre-scaled by 1/8) ----
    qe_kernel<<<(BB * HH * SS) / 64, thr>>>(emb_k);

    // ---- raw scores -> attn region (tensor) ----
    scores_mma_kernel<<<dim3(SS / 128, SS / 128, BB * HH), thr, SC_SMEM>>>(attn);

    // ---- softmax in-place + relative bucket sums ----
    softmax_aw_kernel<<<BB * HH * SS, thr>>>(attn);

    // ---- context: attn @ V + aw @ emb_v, fused tensor GEMM ----
    ctx_mma_kernel<<<dim3(SS / 128, BB * HH), thr, CT_SMEM>>>(attn, emb_v);

    // ---- final_output = ctx @ Wo + bo ----
    split_kernel<<<nA4 / 256, thr>>>((const float4*)pCTX, (uint2*)pAh, (uint2*)pAl);
    transpose_split_kernel<<<gTS, bTS>>>(Wo, pBh, pBl);
    mgemm_kernel<<<gMG, thr, MG_SMEM>>>(pAh, pAl, pBh, pBl, bo, out);
}

// round 15
// speedup vs baseline: 1.0125x; 1.0125x over previous
#include <cuda_runtime.h>
#include <cuda_bf16.h>
#include <cstddef>
#include <cstdint>

// Problem constants (match reference)
#define BB  4
#define SS  1024
#define DD  1024
#define HH  16
#define DKV 64          // DK == DV == 64
#define NR  65          // 2*MAX_REL+1 relative buckets

// ---------------------------------------------------------------------------
// Scratch (static device globals; runtime allocation is forbidden)
// ---------------------------------------------------------------------------
__device__ float g_Q  [(size_t)BB * SS * DD];        // [B,S,H*DK]  projected q
__device__ float g_K  [(size_t)BB * SS * DD];        // [B,S,H*DK]  projected k
__device__ float g_V  [(size_t)BB * SS * DD];        // [B,S,H*DV]  projected v
__device__ float g_CTX[(size_t)BB * SS * DD];        // [B,S,H*DV]  context
__device__ float g_QE [(size_t)BB * HH * SS * NR];   // [BH,S,65]   0.125 * q.emb_k[r]
__device__ float g_AW [(size_t)BB * HH * SS * NR];   // [BH,S,65]   bucket-summed attn

// split-bf16 staging: 3 batched operands (query/key/value or ctx in slot 0)
__device__ __nv_bfloat16 g_Ah[(size_t)3 * BB * SS * DD];
__device__ __nv_bfloat16 g_Al[(size_t)3 * BB * SS * DD];
__device__ __nv_bfloat16 g_Bh[(size_t)3 * DD * DD];
__device__ __nv_bfloat16 g_Bl[(size_t)3 * DD * DD];

// ===========================================================================
// PTX helpers — baseline (non-'a') ISA only: ldmatrix / mma.sync / cp.async
// ===========================================================================
__device__ __forceinline__ uint32_t smem_u32(const void* p) {
    uint32_t a;
    asm("{ .reg .u64 t; cvta.to.shared.u64 t, %1; cvt.u32.u64 %0, t; }"
        : "=r"(a) : "l"(p));
    return a;
}

#define CP_ASYNC16(dst, src) \
    asm volatile("cp.async.cg.shared.global [%0], [%1], 16;" \
                 :: "r"(dst), "l"(src))
#define CP_COMMIT()  asm volatile("cp.async.commit_group;" ::: "memory")
#define CP_WAIT0()   asm volatile("cp.async.wait_group 0;"  ::: "memory")

#define LDSM_X4(r0, r1, r2, r3, addr) \
    asm volatile("ldmatrix.sync.aligned.m8n8.x4.shared.b16 {%0,%1,%2,%3}, [%4];" \
                 : "=r"(r0), "=r"(r1), "=r"(r2), "=r"(r3) : "r"(addr))

// D(f32) += A(bf16,row) @ B(bf16,col);  c[4] in-place accumulate
#define MMA16816(c, a, b) \
    asm volatile("mma.sync.aligned.m16n8k16.row.col.f32.bf16.bf16.f32 " \
                 "{%0,%1,%2,%3}, {%4,%5,%6,%7}, {%8,%9}, {%0,%1,%2,%3};" \
                 : "+f"((c)[0]), "+f"((c)[1]), "+f"((c)[2]), "+f"((c)[3]) \
                 : "r"((a)[0]), "r"((a)[1]), "r"((a)[2]), "r"((a)[3]), \
                   "r"((b)[0]), "r"((b)[1]))

// split one fp32 into hi/lo bf16
__device__ __forceinline__ void split1(float v, __nv_bfloat16& h, __nv_bfloat16& l) {
    h = __float2bfloat16(v);
    l = __float2bfloat16(v - __bfloat162float(h));
}
// split float4 into two packed uint2 (4 bf16 each)
__device__ __forceinline__ void split4(float4 x, uint2& H, uint2& L) {
    __nv_bfloat16 h0, h1, h2, h3, l0, l1, l2, l3;
    split1(x.x, h0, l0); split1(x.y, h1, l1);
    split1(x.z, h2, l2); split1(x.w, h3, l3);
    __nv_bfloat162 ha = __halves2bfloat162(h0, h1), hb = __halves2bfloat162(h2, h3);
    __nv_bfloat162 la = __halves2bfloat162(l0, l1), lb = __halves2bfloat162(l2, l3);
    H.x = *reinterpret_cast<uint32_t*>(&ha); H.y = *reinterpret_cast<uint32_t*>(&hb);
    L.x = *reinterpret_cast<uint32_t*>(&la); L.y = *reinterpret_cast<uint32_t*>(&lb);
}

// ===========================================================================
// Batched split: slot z of (x0,x1,x2) -> g_Ah/g_Al slice z
// ===========================================================================
__global__ __launch_bounds__(256) void split_all_kernel(
    const float4* __restrict__ x0, const float4* __restrict__ x1,
    const float4* __restrict__ x2,
    uint2* __restrict__ hi, uint2* __restrict__ lo)
{
    const int z = blockIdx.y;
    const float4* X = (z == 0) ? x0 : (z == 1) ? x1 : x2;
    const size_t off = (size_t)z * ((size_t)BB * SS * DD / 4);
    int i = blockIdx.x * 256 + threadIdx.x;
    uint2 H, L;
    split4(X[i], H, L);
    hi[off + i] = H; lo[off + i] = L;
}

// Batched W[K,N] fp32 -> [N,K] bf16 hi/lo into slice z
__global__ __launch_bounds__(256) void transpose_split_all_kernel(
    const float* __restrict__ W0, const float* __restrict__ W1,
    const float* __restrict__ W2,
    __nv_bfloat16* __restrict__ th, __nv_bfloat16* __restrict__ tl)
{
    __shared__ float t[32][33];
    const int z = blockIdx.z;
    const float* W = (z == 0) ? W0 : (z == 1) ? W1 : W2;
    const size_t off = (size_t)z * DD * DD;
    const int n0 = blockIdx.x * 32, k0 = blockIdx.y * 32;
    const int tx = threadIdx.x, ty = threadIdx.y;
#pragma unroll
    for (int i = 0; i < 32; i += 8)
        t[ty + i][tx] = W[(size_t)(k0 + ty + i) * DD + n0 + tx];
    __syncthreads();
#pragma unroll
    for (int i = 0; i < 32; i += 8) {
        float v = t[tx][ty + i];
        __nv_bfloat16 h, l; split1(v, h, l);
        th[off + (size_t)(n0 + ty + i) * DD + k0 + tx] = h;
        tl[off + (size_t)(n0 + ty + i) * DD + k0 + tx] = l;
    }
}

// ===========================================================================
// mma.sync split-bf16 GEMM, z-batched: C_z[4096,1024] = A_z @ W_z + bias_z
// CTA tile 128m x 256n, BK=32, double-buffered cp.async, 8 warps (64x64 each).
// 3 passes: Ah@Bh + Ah@Bl + Al@Bh (A-lo frags loaded late to cap reg pressure).
// ===========================================================================
#define MG_M       4096
#define MG_BK      32
#define MG_NCHUNK  (DD / MG_BK)              // 32
#define MG_ROW_B   80                        // padded row pitch (bytes)
#define MG_A_B     (128 * MG_ROW_B)          // 10240 per A tile
#define MG_B_B     (256 * MG_ROW_B)          // 20480 per B tile
#define MG_STAGE_B (2 * MG_A_B + 2 * MG_B_B) // 61440
#define MG_SMEM    (2 * MG_STAGE_B)          // 122880

__global__ __launch_bounds__(256, 1) void mgemm_kernel(
    const __nv_bfloat16* __restrict__ Ah_, const __nv_bfloat16* __restrict__ Al_,
    const __nv_bfloat16* __restrict__ Bh_, const __nv_bfloat16* __restrict__ Bl_,
    const float* b0, const float* b1, const float* b2,
    float* c0, float* c1, float* c2)
{
    extern __shared__ char smem[];
    const uint32_t sbase = smem_u32(smem);
    const int z = blockIdx.z;
    const __nv_bfloat16* Ah = Ah_ + (size_t)z * MG_M * DD;
    const __nv_bfloat16* Al = Al_ + (size_t)z * MG_M * DD;
    const __nv_bfloat16* Bh = Bh_ + (size_t)z * DD * DD;
    const __nv_bfloat16* Bl = Bl_ + (size_t)z * DD * DD;
    const float* bias = (z == 0) ? b0 : (z == 1) ? b1 : b2;
    float*       C    = (z == 0) ? c0 : (z == 1) ? c1 : c2;

    const int tid  = threadIdx.x;
    const int lane = tid & 31, wid = tid >> 5;
    const int wm   = wid >> 2, wn = wid & 3;       // 2 x 4 warp grid (64x64)
    const int m0   = blockIdx.y * 128;
    const int n0   = blockIdx.x * 256;

    // smem tile offsets within a stage: Ah, Al, Bh, Bl
    // A: 128 rows; B: 256 rows. pitch 80 B.
    auto load_chunk = [&](int i, int st) {
        const int k0 = i * MG_BK;
        const uint32_t sb = sbase + st * MG_STAGE_B;
        // A tiles: 512 16B-vectors each
#pragma unroll
        for (int p = 0; p < 2; p++) {
            int idx = tid + p * 256;
            int r = idx >> 2, c = idx & 3;
            const size_t go = (size_t)(m0 + r) * DD + k0 + c * 8;
            CP_ASYNC16(sb + r * MG_ROW_B + c * 16, Ah + go);
            CP_ASYNC16(sb + MG_A_B + r * MG_ROW_B + c * 16, Al + go);
        }
        // B tiles: 1024 16B-vectors each
#pragma unroll
        for (int p = 0; p < 4; p++) {
            int idx = tid + p * 256;
            int r = idx >> 2, c = idx & 3;
            const size_t go = (size_t)(n0 + r) * DD + k0 + c * 8;
            CP_ASYNC16(sb + 2 * MG_A_B + r * MG_ROW_B + c * 16, Bh + go);
            CP_ASYNC16(sb + 2 * MG_A_B + MG_B_B + r * MG_ROW_B + c * 16, Bl + go);
        }
    };

    float acc[4][8][4] = {};                       // 128 f32 / thread
    load_chunk(0, 0);
    CP_COMMIT();

    const int lr = lane & 15, lh = lane >> 4;

    for (int i = 0; i < MG_NCHUNK; i++) {
        const int st = i & 1;
        CP_WAIT0();
        __syncthreads();
        if (i + 1 < MG_NCHUNK) { load_chunk(i + 1, st ^ 1); CP_COMMIT(); }

        const uint32_t stb = sbase + st * MG_STAGE_B;
#pragma unroll
        for (int ks = 0; ks < 2; ks++) {
            uint32_t af[4][4], bhf[8][2], blf[8][2];
            const uint32_t kb = ks * 32 + lh * 16;
            // B frags (hi + lo): 8 n8-frags each
#pragma unroll
            for (int hh = 0; hh < 4; hh++) {
                uint32_t rowb = (wn * 64 + hh * 16 + lr) * MG_ROW_B + kb;
                uint32_t r0, r1, r2, r3;
                LDSM_X4(r0, r1, r2, r3, stb + 2 * MG_A_B + rowb);
                bhf[hh * 2][0] = r0; bhf[hh * 2 + 1][0] = r1;
                bhf[hh * 2][1] = r2; bhf[hh * 2 + 1][1] = r3;
                LDSM_X4(r0, r1, r2, r3, stb + 2 * MG_A_B + MG_B_B + rowb);
                blf[hh * 2][0] = r0; blf[hh * 2 + 1][0] = r1;
                blf[hh * 2][1] = r2; blf[hh * 2 + 1][1] = r3;
            }
            // A-hi frags; passes 1 & 2
#pragma unroll
            for (int f = 0; f < 4; f++) {
                uint32_t rowb = (wm * 64 + f * 16 + lr) * MG_ROW_B + kb;
                LDSM_X4(af[f][0], af[f][1], af[f][2], af[f][3], stb + rowb);
            }
#pragma unroll
            for (int mf = 0; mf < 4; mf++)
#pragma unroll
                for (int nf = 0; nf < 8; nf++)
                    MMA16816(acc[mf][nf], af[mf], bhf[nf]);
#pragma unroll
            for (int mf = 0; mf < 4; mf++)
#pragma unroll
                for (int nf = 0; nf < 8; nf++)
                    MMA16816(acc[mf][nf], af[mf], blf[nf]);
            // A-lo frags (overwrite af); pass 3
#pragma unroll
            for (int f = 0; f < 4; f++) {
                uint32_t rowb = (wm * 64 + f * 16 + lr) * MG_ROW_B + kb;
                LDSM_X4(af[f][0], af[f][1], af[f][2], af[f][3],
                        stb + MG_A_B + rowb);
            }
#pragma unroll
            for (int mf = 0; mf < 4; mf++)
#pragma unroll
                for (int nf = 0; nf < 8; nf++)
                    MMA16816(acc[mf][nf], af[mf], bhf[nf]);
        }
        __syncthreads();
    }

    const int g = lane >> 2, tq = lane & 3;
#pragma unroll
    for (int mf = 0; mf < 4; mf++) {
        const int row = m0 + wm * 64 + mf * 16 + g;
#pragma unroll
        for (int nf = 0; nf < 8; nf++) {
            const int col = n0 + wn * 64 + nf * 8 + tq * 2;
            const float2 bv = *reinterpret_cast<const float2*>(bias + col);
            float2 o0, o1;
            o0.x = acc[mf][nf][0] + bv.x; o0.y = acc[mf][nf][1] + bv.y;
            o1.x = acc[mf][nf][2] + bv.x; o1.y = acc[mf][nf][3] + bv.y;
            *reinterpret_cast<float2*>(C + (size_t)row * DD + col)       = o0;
            *reinterpret_cast<float2*>(C + (size_t)(row + 8) * DD + col) = o1;
        }
    }
}

// ---------------------------------------------------------------------------
// qe[bh,q,r] = 0.125 * sum_d Q[b,q,h*64+d] * emb_k[r,d]
// ---------------------------------------------------------------------------
__global__ __launch_bounds__(256) void qe_kernel(const float* __restrict__ emb_k)
{
    __shared__ float Qs[64][65];
    __shared__ float E [NR][66];
    const int tid = threadIdx.x;
    const int g0  = blockIdx.x * 64;
    const int bh  = g0 / SS;
    const int qb  = g0 % SS;
    const int b   = bh / HH, h = bh % HH;

    for (int idx = tid; idx < NR * 64; idx += 256) {
        int r = idx >> 6, d = idx & 63;
        E[r][d] = emb_k[idx];
    }
    for (int idx = tid; idx < 64 * 64; idx += 256) {
        int r = idx >> 6, d = idx & 63;
        Qs[r][d] = g_Q[(size_t)(b * SS + qb + r) * DD + h * DKV + d];
    }
    __syncthreads();

    const int ty = tid >> 4, tx = tid & 15;
    float acc[4][4] = {};
    float acc4[4]   = {};
#pragma unroll 8
    for (int d = 0; d < 64; d++) {
        float qv[4];
#pragma unroll
        for (int i = 0; i < 4; i++) qv[i] = Qs[4 * ty + i][d];
#pragma unroll
        for (int j = 0; j < 4; j++) {
            float ev = E[tx + 16 * j][d];
#pragma unroll
            for (int i = 0; i < 4; i++) acc[i][j] = fmaf(qv[i], ev, acc[i][j]);
        }
        if (tx == 0) {
            float e4 = E[64][d];
#pragma unroll
            for (int i = 0; i < 4; i++) acc4[i] = fmaf(qv[i], e4, acc4[i]);
        }
    }
#pragma unroll
    for (int i = 0; i < 4; i++) {
        size_t rowo = (size_t)(g0 + 4 * ty + i) * NR;
#pragma unroll
        for (int j = 0; j < 4; j++)
            g_QE[rowo + tx + 16 * j] = 0.125f * acc[i][j];
        if (tx == 0) g_QE[rowo + 64] = 0.125f * acc4[i];
    }
}

// ===========================================================================
// scores (tensor): attn_raw[bh,q,k] = (Q/8).K + qe_scaled[q, clip(k-q)+32]
// ===========================================================================
#define SC_PITCH  144
#define SC_TILE_B (128 * SC_PITCH)
#define SC_QE_OFF (4 * SC_TILE_B)
#define SC_SMEM   (SC_QE_OFF + 128 * 66 * 4)

__global__ __launch_bounds__(256, 1) void scores_mma_kernel(float* __restrict__ attn)
{
    extern __shared__ char smem[];
    const uint32_t sbase = smem_u32(smem);
    float* qe_s = reinterpret_cast<float*>(smem + SC_QE_OFF);
    const int tid  = threadIdx.x;
    const int lane = tid & 31, wid = tid >> 5;
    const int wm   = wid >> 2, wn = wid & 3;
    const int bh = blockIdx.z;
    const int b  = bh / HH, h = bh % HH;
    const int q0 = blockIdx.y * 128;
    const int k0 = blockIdx.x * 128;

#pragma unroll
    for (int p = 0; p < 8; p++) {
        int idx = tid + p * 256;
        int r = idx >> 4, c = idx & 15;
        float4 q4 = *reinterpret_cast<const float4*>(
            &g_Q[(size_t)(b * SS + q0 + r) * DD + h * DKV + c * 4]);
        q4.x *= 0.125f; q4.y *= 0.125f; q4.z *= 0.125f; q4.w *= 0.125f;
        uint2 H, L; split4(q4, H, L);
        *reinterpret_cast<uint2*>(smem + 0 * SC_TILE_B + r * SC_PITCH + c * 8) = H;
        *reinterpret_cast<uint2*>(smem + 1 * SC_TILE_B + r * SC_PITCH + c * 8) = L;
        float4 k4 = *reinterpret_cast<const float4*>(
            &g_K[(size_t)(b * SS + k0 + r) * DD + h * DKV + c * 4]);
        split4(k4, H, L);
        *reinterpret_cast<uint2*>(smem + 2 * SC_TILE_B + r * SC_PITCH + c * 8) = H;
        *reinterpret_cast<uint2*>(smem + 3 * SC_TILE_B + r * SC_PITCH + c * 8) = L;
    }
#pragma unroll
    for (int p = 0; p < 33; p++) {
        int idx = tid + p * 256;
        if (idx < 128 * NR) {
            int r = idx / NR, rr = idx - r * NR;
            qe_s[r * 66 + rr] = g_QE[((size_t)bh * SS + q0 + r) * NR + rr];
        }
    }
    __syncthreads();

    float acc[4][4][4] = {};
    const int lr = lane & 15, lh = lane >> 4;
#pragma unroll
    for (int ks = 0; ks < 4; ks++) {
        uint32_t ah[4][4], al[4][4], bhf[4][2], blf[4][2];
        const uint32_t kb = ks * 32 + lh * 16;
#pragma unroll
        for (int f = 0; f < 4; f++) {
            uint32_t rowb = (wm * 64 + f * 16 + lr) * SC_PITCH + kb;
            LDSM_X4(ah[f][0], ah[f][1], ah[f][2], ah[f][3], sbase + 0 * SC_TILE_B + rowb);
            LDSM_X4(al[f][0], al[f][1], al[f][2], al[f][3], sbase + 1 * SC_TILE_B + rowb);
        }
#pragma unroll
        for (int hh = 0; hh < 2; hh++) {
            uint32_t rowb = (wn * 32 + hh * 16 + lr) * SC_PITCH + kb;
            uint32_t r0, r1, r2, r3;
            LDSM_X4(r0, r1, r2, r3, sbase + 2 * SC_TILE_B + rowb);
            bhf[hh * 2][0] = r0; bhf[hh * 2 + 1][0] = r1;
            bhf[hh * 2][1] = r2; bhf[hh * 2 + 1][1] = r3;
            LDSM_X4(r0, r1, r2, r3, sbase + 3 * SC_TILE_B + rowb);
            blf[hh * 2][0] = r0; blf[hh * 2 + 1][0] = r1;
            blf[hh * 2][1] = r2; blf[hh * 2 + 1][1] = r3;
        }
#pragma unroll
        for (int mf = 0; mf < 4; mf++)
#pragma unroll
            for (int nf = 0; nf < 4; nf++)
                MMA16816(acc[mf][nf], ah[mf], bhf[nf]);
#pragma unroll
        for (int mf = 0; mf < 4; mf++)
#pragma unroll
            for (int nf = 0; nf < 4; nf++)
                MMA16816(acc[mf][nf], ah[mf], blf[nf]);
#pragma unroll
        for (int mf = 0; mf < 4; mf++)
#pragma unroll
            for (int nf = 0; nf < 4; nf++)
                MMA16816(acc[mf][nf], al[mf], bhf[nf]);
    }

    const int g = lane >> 2, tq = lane & 3;
    const int brel = k0 - q0;
#pragma unroll
    for (int mf = 0; mf < 4; mf++) {
        const int row  = wm * 64 + mf * 16 + g;
#pragma unroll
        for (int nf = 0; nf < 4; nf++) {
            const int col = wn * 32 + nf * 8 + tq * 2;
            int r0 = brel + col - row;
            int i00 = min(max(r0,     -32), 32) + 32;
            int i01 = min(max(r0 + 1, -32), 32) + 32;
            int i10 = min(max(r0 - 8, -32), 32) + 32;
            int i11 = min(max(r0 - 7, -32), 32) + 32;
            float2 o0, o1;
            o0.x = acc[mf][nf][0] + qe_s[row * 66 + i00];
            o0.y = acc[mf][nf][1] + qe_s[row * 66 + i01];
            o1.x = acc[mf][nf][2] + qe_s[(row + 8) * 66 + i10];
            o1.y = acc[mf][nf][3] + qe_s[(row + 8) * 66 + i11];
            *reinterpret_cast<float2*>(
                &attn[((size_t)bh * SS + q0 + row) * SS + k0 + col]) = o0;
            *reinterpret_cast<float2*>(
                &attn[((size_t)bh * SS + q0 + row + 8) * SS + k0 + col]) = o1;
        }
    }
}

// ---------------------------------------------------------------------------
// FMA-pipe exp (degree-7, rel err ~1.3e-6). Valid for x <= 0.
// ---------------------------------------------------------------------------
__device__ __forceinline__ float fast_exp_neg(float x)
{
    x = fmaxf(x, -87.0f);
    float y = x * 1.4426950408889634f;
    float n = floorf(y);
    float f = y - n;
    float p = 1.5252734e-5f;
    p = fmaf(p, f, 1.5403530e-4f);
    p = fmaf(p, f, 1.3333558e-3f);
    p = fmaf(p, f, 9.6181291e-3f);
    p = fmaf(p, f, 5.5504109e-2f);
    p = fmaf(p, f, 2.4022651e-1f);
    p = fmaf(p, f, 6.9314718e-1f);
    p = fmaf(p, f, 1.0f);
    int e = (int)n;
    float sc = __int_as_float((e + 127) << 23);
    return p * sc;
}

// ---------------------------------------------------------------------------
// Row softmax in-place + relative-bucket accumulation.
// ---------------------------------------------------------------------------
__global__ __launch_bounds__(256) void softmax_aw_kernel(float* __restrict__ attn)
{
    const size_t g = blockIdx.x;
    const int q   = (int)(g & (SS - 1));
    const int tid = threadIdx.x;
    float* row = attn + g * SS;

    __shared__ float red[256];
    __shared__ float aw_s[NR];

    float v[4];
    float m = -1e30f;
#pragma unroll
    for (int i = 0; i < 4; i++) {
        v[i] = row[tid + i * 256];
        m = fmaxf(m, v[i]);
    }
    red[tid] = m; __syncthreads();
    for (int s = 128; s > 0; s >>= 1) {
        if (tid < s) red[tid] = fmaxf(red[tid], red[tid + s]);
        __syncthreads();
    }
    m = red[0]; __syncthreads();

    float sum = 0.f;
#pragma unroll
    for (int i = 0; i < 4; i++) {
        v[i] = fast_exp_neg(v[i] - m);
        sum += v[i];
    }
    red[tid] = sum; __syncthreads();
    for (int s = 128; s > 0; s >>= 1) {
        if (tid < s) red[tid] += red[tid + s];
        __syncthreads();
    }
    const float inv = 1.0f / red[0];
    __syncthreads();

    if (tid < NR) aw_s[tid] = 0.f;
    __syncthreads();

    float l0 = 0.f, l64 = 0.f;
#pragma unroll
    for (int i = 0; i < 4; i++) {
        int k = tid + i * 256;
        float p = v[i] * inv;
        row[k] = p;
        int dlt = k - q;
        if (dlt <= -32)      l0  += p;
        else if (dlt >= 32)  l64 += p;
        else                 aw_s[dlt + 32] = p;
    }

    red[tid] = l0; __syncthreads();
    for (int s = 128; s > 0; s >>= 1) {
        if (tid < s) red[tid] += red[tid + s];
        __syncthreads();
    }
    float t0 = red[0]; __syncthreads();

    red[tid] = l64; __syncthreads();
    for (int s = 128; s > 0; s >>= 1) {
        if (tid < s) red[tid] += red[tid + s];
        __syncthreads();
    }
    float t64 = red[0]; __syncthreads();

    if (tid == 0) { aw_s[0] += t0; aw_s[NR - 1] += t64; }
    __syncthreads();

    if (tid < NR) g_AW[g * NR + tid] = aw_s[tid];
}

// ===========================================================================
// ctx (tensor): ctx = attn @ V + aw @ emb_v (fused, K extended 1024->1120)
// ===========================================================================
#define CT_PITCH   80
#define CT_AT_B    (128 * CT_PITCH)
#define CT_VT_B    (64 * CT_PITCH)
#define CT_STAGE_B (2 * CT_AT_B + 2 * CT_VT_B)
#define CT_SMEM    (2 * CT_STAGE_B)
#define CT_NCHUNK  35

__global__ __launch_bounds__(256, 1) void ctx_mma_kernel(
    const float* __restrict__ attn, const float* __restrict__ emb_v)
{
    extern __shared__ char smem[];
    const uint32_t sbase = smem_u32(smem);
    const int tid  = threadIdx.x;
    const int lane = tid & 31, wid = tid >> 5;
    const int wm   = wid & 3, wn = wid >> 2;
    const int bh = blockIdx.y;
    const int b  = bh / HH, h = bh % HH;
    const int q0 = blockIdx.x * 128;

    float rA[16], rV[8];

    auto ld = [&](int i) {
        if (i < 32) {
#pragma unroll
            for (int p = 0; p < 4; p++) {
                int idx = tid + p * 256;
                int r = idx >> 3, c = idx & 7;
                float4 v = *reinterpret_cast<const float4*>(
                    &attn[((size_t)bh * SS + q0 + r) * SS + i * 32 + c * 4]);
                rA[p * 4] = v.x; rA[p * 4 + 1] = v.y;
                rA[p * 4 + 2] = v.z; rA[p * 4 + 3] = v.w;
            }
#pragma unroll
            for (int p = 0; p < 2; p++) {
                int idx = tid + p * 256;
                int k = idx >> 4, c = idx & 15;
                float4 v = *reinterpret_cast<const float4*>(
                    &g_V[(size_t)(b * SS + i * 32 + k) * DD + h * DKV + c * 4]);
                rV[p * 4] = v.x; rV[p * 4 + 1] = v.y;
                rV[p * 4 + 2] = v.z; rV[p * 4 + 3] = v.w;
            }
        } else {
            const int kb = (i - 32) * 32;
#pragma unroll
            for (int p = 0; p < 16; p++) {
                int idx = tid + p * 256;
                int r = idx >> 5, c = idx & 31;
                int kl = kb + c;
                rA[p] = (kl < NR)
                    ? g_AW[((size_t)bh * SS + q0 + r) * NR + kl] : 0.f;
            }
#pragma unroll
            for (int p = 0; p < 8; p++) {
                int idx = tid + p * 256;
                int k = idx >> 6, d = idx & 63;
                int kl = kb + k;
                rV[p] = (kl < NR) ? emb_v[kl * DKV + d] : 0.f;
            }
        }
    };

    auto st = [&](int i, int s) {
        char* sb = smem + s * CT_STAGE_B;
        if (i < 32) {
#pragma unroll
            for (int p = 0; p < 4; p++) {
                int idx = tid + p * 256;
                int r = idx >> 3, c = idx & 7;
                float4 v = make_float4(rA[p * 4], rA[p * 4 + 1],
                                       rA[p * 4 + 2], rA[p * 4 + 3]);
                uint2 H, L; split4(v, H, L);
                *reinterpret_cast<uint2*>(sb + r * CT_PITCH + c * 8) = H;
                *reinterpret_cast<uint2*>(sb + CT_AT_B + r * CT_PITCH + c * 8) = L;
            }
#pragma unroll
            for (int p = 0; p < 2; p++) {
                int idx = tid + p * 256;
                int k = idx >> 4, c = idx & 15;
#pragma unroll
                for (int j = 0; j < 4; j++) {
                    __nv_bfloat16 hh, ll; split1(rV[p * 4 + j], hh, ll);
                    int d = c * 4 + j;
                    *reinterpret_cast<__nv_bfloat16*>(
                        sb + 2 * CT_AT_B + d * CT_PITCH + k * 2) = hh;
                    *reinterpret_cast<__nv_bfloat16*>(
                        sb + 2 * CT_AT_B + CT_VT_B + d * CT_PITCH + k * 2) = ll;
                }
            }
        } else {
#pragma unroll
            for (int p = 0; p < 16; p++) {
                int idx = tid + p * 256;
                int r = idx >> 5, c = idx & 31;
                __nv_bfloat16 hh, ll; split1(rA[p], hh, ll);
                *reinterpret_cast<__nv_bfloat16*>(sb + r * CT_PITCH + c * 2) = hh;
                *reinterpret_cast<__nv_bfloat16*>(
                    sb + CT_AT_B + r * CT_PITCH + c * 2) = ll;
            }
#pragma unroll
            for (int p = 0; p < 8; p++) {
                int idx = tid + p * 256;
                int k = idx >> 6, d = idx & 63;
                __nv_bfloat16 hh, ll; split1(rV[p], hh, ll);
                *reinterpret_cast<__nv_bfloat16*>(
                    sb + 2 * CT_AT_B + d * CT_PITCH + k * 2) = hh;
                *reinterpret_cast<__nv_bfloat16*>(
                    sb + 2 * CT_AT_B + CT_VT_B + d * CT_PITCH + k * 2) = ll;
            }
        }
    };

    ld(0); st(0, 0);
    __syncthreads();

    float acc[2][4][4] = {};
    const int lr = lane & 15, lh = lane >> 4;

    for (int i = 0; i < CT_NCHUNK; i++) {
        const int s = i & 1;
        if (i + 1 < CT_NCHUNK) ld(i + 1);

        const uint32_t stb = sbase + s * CT_STAGE_B;
#pragma unroll
        for (int ks = 0; ks < 2; ks++) {
            uint32_t ah[2][4], al[2][4], bhf[4][2], blf[4][2];
            const uint32_t kb = ks * 32 + lh * 16;
#pragma unroll
            for (int f = 0; f < 2; f++) {
                uint32_t rowb = (wm * 32 + f * 16 + lr) * CT_PITCH + kb;
                LDSM_X4(ah[f][0], ah[f][1], ah[f][2], ah[f][3], stb + rowb);
                LDSM_X4(al[f][0], al[f][1], al[f][2], al[f][3],
                        stb + CT_AT_B + rowb);
            }
#pragma unroll
            for (int hh = 0; hh < 2; hh++) {
                uint32_t rowb = (wn * 32 + hh * 16 + lr) * CT_PITCH + kb;
                uint32_t r0, r1, r2, r3;
                LDSM_X4(r0, r1, r2, r3, stb + 2 * CT_AT_B + rowb);
                bhf[hh * 2][0] = r0; bhf[hh * 2 + 1][0] = r1;
                bhf[hh * 2][1] = r2; bhf[hh * 2 + 1][1] = r3;
                LDSM_X4(r0, r1, r2, r3, stb + 2 * CT_AT_B + CT_VT_B + rowb);
                blf[hh * 2][0] = r0; blf[hh * 2 + 1][0] = r1;
                blf[hh * 2][1] = r2; blf[hh * 2 + 1][1] = r3;
            }
#pragma unroll
            for (int mf = 0; mf < 2; mf++)
#pragma unroll
                for (int nf = 0; nf < 4; nf++)
                    MMA16816(acc[mf][nf], ah[mf], bhf[nf]);
#pragma unroll
            for (int mf = 0; mf < 2; mf++)
#pragma unroll
                for (int nf = 0; nf < 4; nf++)
                    MMA16816(acc[mf][nf], ah[mf], blf[nf]);
#pragma unroll
            for (int mf = 0; mf < 2; mf++)
#pragma unroll
                for (int nf = 0; nf < 4; nf++)
                    MMA16816(acc[mf][nf], al[mf], bhf[nf]);
        }
        if (i + 1 < CT_NCHUNK) st(i + 1, s ^ 1);
        __syncthreads();
    }

    const int g = lane >> 2, tq = lane & 3;
#pragma unroll
    for (int mf = 0; mf < 2; mf++) {
        const int row = q0 + wm * 32 + mf * 16 + g;
#pragma unroll
        for (int nf = 0; nf < 4; nf++) {
            const int col = wn * 32 + nf * 8 + tq * 2;
            float2 o0 = make_float2(acc[mf][nf][0], acc[mf][nf][1]);
            float2 o1 = make_float2(acc[mf][nf][2], acc[mf][nf][3]);
            *reinterpret_cast<float2*>(
                &g_CTX[(size_t)(b * SS + row) * DD + h * DKV + col]) = o0;
            *reinterpret_cast<float2*>(
                &g_CTX[(size_t)(b * SS + row + 8) * DD + h * DKV + col]) = o1;
        }
    }
}

// ---------------------------------------------------------------------------
// kernel_launch
// Inputs: key, value, query, Wk, bk, Wq, bq, Wv, bv, Wo, bo, emb_k, emb_v
// Output: concat(final_output [B*S*D], attn [B*H*S*S]) float32
// ---------------------------------------------------------------------------
extern "C" void kernel_launch(void* const* d_in, const int* in_sizes, int n_in,
                              void* d_out, int out_size)
{
    (void)in_sizes; (void)n_in; (void)out_size;
    const float* key   = (const float*)d_in[0];
    const float* value = (const float*)d_in[1];
    const float* query = (const float*)d_in[2];
    const float* Wk    = (const float*)d_in[3];
    const float* bk    = (const float*)d_in[4];
    const float* Wq    = (const float*)d_in[5];
    const float* bq    = (const float*)d_in[6];
    const float* Wv    = (const float*)d_in[7];
    const float* bv    = (const float*)d_in[8];
    const float* Wo    = (const float*)d_in[9];
    const float* bo    = (const float*)d_in[10];
    const float* emb_k = (const float*)d_in[11];
    const float* emb_v = (const float*)d_in[12];

    float* out  = (float*)d_out;
    float* attn = out + (size_t)BB * SS * DD;

    float *pQ, *pK, *pV, *pCTX;
    cudaGetSymbolAddress((void**)&pQ,   g_Q);
    cudaGetSymbolAddress((void**)&pK,   g_K);
    cudaGetSymbolAddress((void**)&pV,   g_V);
    cudaGetSymbolAddress((void**)&pCTX, g_CTX);
    __nv_bfloat16 *pAh, *pAl, *pBh, *pBl;
    cudaGetSymbolAddress((void**)&pAh, g_Ah);
    cudaGetSymbolAddress((void**)&pAl, g_Al);
    cudaGetSymbolAddress((void**)&pBh, g_Bh);
    cudaGetSymbolAddress((void**)&pBl, g_Bl);

    cudaFuncSetAttribute(mgemm_kernel,
                         cudaFuncAttributeMaxDynamicSharedMemorySize, MG_SMEM);
    cudaFuncSetAttribute(scores_mma_kernel,
                         cudaFuncAttributeMaxDynamicSharedMemorySize, SC_SMEM);
    cudaFuncSetAttribute(ctx_mma_kernel,
                         cudaFuncAttributeMaxDynamicSharedMemorySize, CT_SMEM);

    const int M = BB * SS;                       // 4096
    dim3 thr(256);
    const int nA4 = (M * DD) / 4;

    // ---- batched stage: split (query,key,value), transpose (Wq,Wk,Wv) ----
    split_all_kernel<<<dim3(nA4 / 256, 3), thr>>>(
        (const float4*)query, (const float4*)key, (const float4*)value,
        (uint2*)pAh, (uint2*)pAl);
    transpose_split_all_kernel<<<dim3(DD / 32, DD / 32, 3), dim3(32, 8)>>>(
        Wq, Wk, Wv, pBh, pBl);

    // ---- all three projections in ONE z-batched GEMM launch ----
    mgemm_kernel<<<dim3(DD / 256, M / 128, 3), thr, MG_SMEM>>>(
        pAh, pAl, pBh, pBl, bq, bk, bv, pQ, pK, pV);

    // ---- relative-key projections qe (pre-scaled by 1/8) ----
    qe_kernel<<<(BB * HH * SS) / 64, thr>>>(emb_k);

    // ---- raw scores -> attn region (tensor) ----
    scores_mma_kernel<<<dim3(SS / 128, SS / 128, BB * HH), thr, SC_SMEM>>>(attn);

    // ---- softmax in-place + relative bucket sums ----
    softmax_aw_kernel<<<BB * HH * SS, thr>>>(attn);

    // ---- context: attn @ V + aw @ emb_v, fused tensor GEMM ----
    ctx_mma_kernel<<<dim3(SS / 128, BB * HH), thr, CT_SMEM>>>(attn, emb_v);

    // ---- final_output = ctx @ Wo + bo ----
    split_all_kernel<<<dim3(nA4 / 256, 1), thr>>>(
        (const float4*)pCTX, (const float4*)pCTX, (const float4*)pCTX,
        (uint2*)pAh, (uint2*)pAl);
    transpose_split_all_kernel<<<dim3(DD / 32, DD / 32, 1), dim3(32, 8)>>>(
        Wo, Wo, Wo, pBh, pBl);
    mgemm_kernel<<<dim3(DD / 256, M / 128, 1), thr, MG_SMEM>>>(
        pAh, pAl, pBh, pBl, bo, bo, bo, out, out, out);
}